// round 1
// baseline (speedup 1.0000x reference)
#include <cuda_runtime.h>

#define CC 64
#define TT 256
#define VV 25
#define NN 128
#define TCHUNK 32
#define POSB 800            /* TCHUNK*VV */
#define NBLK 8              /* TT/TCHUNK */
#define NPOS 819200.0f      /* NN*TT*VV */
#define TOTEL 52428800      /* NN*CC*TT*VV */

// Scratch / folded parameters (device globals: no runtime allocation)
__device__ __align__(16) float g_W[VV * CC * CC];   // [v][c][o]
__device__ __align__(16) float g_B[CC];
__device__ float g_sum[CC];
__device__ float g_sumsq[CC];
__device__ __align__(16) float g_scale[CC];
__device__ __align__(16) float g_shift[CC];
__device__ float g_hidden[TOTEL];                   // blocked layout: [blk(1024)][v(25)][o(64)][tl(32)]

__device__ __forceinline__ void ffma2(unsigned long long& d, unsigned long long a,
                                      unsigned long long b) {
    asm("fma.rn.f32x2 %0, %1, %2, %0;" : "+l"(d) : "l"(a), "l"(b));
}

// ---------------------------------------------------------------------------
// k0: fold attention rowsums into per-vertex weights.
//   s_i[v] = 1 + sum_w (A[i,v,w] + graph_attn[i,v,w])   (softmax rows sum to 1)
//   W[v][c][o] = sum_i s_i[v] * g_w[i][o][c],  B[o] = sum_i g_b[i][o]
// Also zeroes the stat accumulators for this graph replay.
// ---------------------------------------------------------------------------
__global__ void k0(const float* __restrict__ A, const float* __restrict__ GA,
                   const float* __restrict__ gw, const float* __restrict__ gb) {
    __shared__ float s_sh[3 * 25];
    int tid = threadIdx.x;
    if (tid < CC) {
        g_sum[tid] = 0.f;
        g_sumsq[tid] = 0.f;
        float b = 0.f;
        for (int i = 0; i < 3; i++) b += gb[i * CC + tid];
        g_B[tid] = b;
    }
    if (tid < 75) {
        const float* a = A + tid * 25;
        const float* g = GA + tid * 25;
        float s = 1.f;
        for (int w = 0; w < 25; w++) s += a[w] + g[w];
        s_sh[tid] = s;
    }
    __syncthreads();
    for (int idx = tid; idx < VV * CC * CC; idx += blockDim.x) {
        int v = idx >> 12;
        int r = idx & 4095;
        int c = r >> 6;
        int o = r & 63;
        float w = 0.f;
        for (int i = 0; i < 3; i++) w += s_sh[i * 25 + v] * gw[(i * CC + o) * CC + c];
        g_W[idx] = w;
    }
}

// ---------------------------------------------------------------------------
// k1: main compute. Block = (t-chunk tc, batch n). 512 threads, 16 warps.
// Stage x tile xs[c][pos] (64 x 800 floats) in smem. Warp -> vertex v
// (two rounds: v = warp, warp+16), lane -> local t. Each lane computes all 64
// output channels for its position as 32 packed f32x2 accumulators
// (o-pairs in the packed lanes; weights pre-laid [v][c][o] so a 16B load
// yields two ready-packed f32x2 weight operands — no repack movs).
// Stores raw hidden to scratch, coalesced (lane-major per o).
// ---------------------------------------------------------------------------
__global__ void __launch_bounds__(512, 1) k1(const float* __restrict__ x) {
    extern __shared__ float xs[];   // [64][800]
    int tid = threadIdx.x;
    int tc = blockIdx.x, n = blockIdx.y;
    const float* xblk = x + (size_t)n * CC * TT * VV + tc * POSB;

    // coalesced float4 staging: 64 channels x 200 float4 each
    for (int e = tid; e < CC * (POSB / 4); e += 512) {
        int c = e / (POSB / 4), q = e % (POSB / 4);
        ((float4*)xs)[c * (POSB / 4) + q] =
            ((const float4*)(xblk + (size_t)c * (TT * VV)))[q];
    }
    __syncthreads();

    int warp = tid >> 5, lane = tid & 31;
    for (int v = warp; v < VV; v += 16) {
        unsigned long long acc[32];
#pragma unroll
        for (int j = 0; j < 32; j++) {
            float2 b = ((const float2*)g_B)[j];
            asm("mov.b64 %0, {%1,%2};" : "=l"(acc[j]) : "f"(b.x), "f"(b.y));
        }
        const float* xcol = xs + lane * VV + v;           // stride 25: conflict-free
        const ulonglong2* wv = (const ulonglong2*)(g_W + v * (CC * CC));
#pragma unroll 2
        for (int c = 0; c < CC; c++) {
            float xv = xcol[c * POSB];
            unsigned long long x2;
            asm("mov.b64 %0, {%1,%1};" : "=l"(x2) : "f"(xv));
#pragma unroll
            for (int j = 0; j < 16; j++) {
                ulonglong2 w = wv[c * 16 + j];            // = {W[o4j],W[o4j+1]},{W[o4j+2],W[o4j+3]}
                ffma2(acc[2 * j], w.x, x2);
                ffma2(acc[2 * j + 1], w.y, x2);
            }
        }
        // store raw hidden: scratch[blk][v][o][lane], coalesced per o
        float* hdst = g_hidden + (((size_t)(n * NBLK + tc) * VV + v) * CC) * TCHUNK + lane;
#pragma unroll
        for (int j = 0; j < 32; j++) {
            float h0, h1;
            asm("mov.b64 {%0,%1}, %2;" : "=f"(h0), "=f"(h1) : "l"(acc[j]));
            hdst[(2 * j) * TCHUNK] = h0;
            hdst[(2 * j + 1) * TCHUNK] = h1;
        }
    }
}

// ---------------------------------------------------------------------------
// k2: per-channel sum / sumsq over scratch. Each warp owns one channel o
// (warp_id % 64), grid-strides over the 25600 (blk,v) bases, reading its
// 32-float coalesced row, then one shfl-reduce + one atomic per warp.
// 1184 blocks * 8 warps = 9472 warps = 148 warp-groups of 64.
// ---------------------------------------------------------------------------
__global__ void k2() {
    int gwid = (blockIdx.x * blockDim.x + threadIdx.x) >> 5;
    int lane = threadIdx.x & 31;
    int o = gwid & 63;
    float s = 0.f, q = 0.f;
    for (int base = gwid >> 6; base < 1024 * VV; base += 148) {
        float val = g_hidden[((size_t)base * CC + o) * TCHUNK + lane];
        s += val;
        q += val * val;
    }
#pragma unroll
    for (int d = 16; d; d >>= 1) {
        s += __shfl_xor_sync(0xffffffffu, s, d);
        q += __shfl_xor_sync(0xffffffffu, q, d);
    }
    if (lane == 0) {
        atomicAdd(&g_sum[o], s);
        atomicAdd(&g_sumsq[o], q);
    }
}

// ---------------------------------------------------------------------------
// kbn: fold batch-norm (training-mode biased stats) into scale/shift.
// ---------------------------------------------------------------------------
__global__ void kbn(const float* __restrict__ gamma, const float* __restrict__ beta) {
    int o = threadIdx.x;
    if (o < CC) {
        float m = g_sum[o] * (1.0f / NPOS);
        float var = g_sumsq[o] * (1.0f / NPOS) - m * m;
        float r = rsqrtf(var + 1e-5f);
        g_scale[o] = gamma[o] * r;
        g_shift[o] = beta[o] - m * gamma[o] * r;
    }
}

// ---------------------------------------------------------------------------
// k3: epilogue. Per block (tc, n): pull the contiguous scratch chunk through
// smem with a transpose-on-write (stride-25 stores: conflict-free), then
// fused BN + residual + relu with fully coalesced x reads / out writes.
// Split into two o-halves so smem = 100 KB -> 2 blocks/SM overlap.
// ---------------------------------------------------------------------------
__global__ void __launch_bounds__(800, 2) k3(const float* __restrict__ x,
                                             float* __restrict__ out) {
    extern __shared__ float hs[];   // [32][800]
    int tid = threadIdx.x;
    int tc = blockIdx.x, n = blockIdx.y;
    size_t xoff = (size_t)n * CC * TT * VV + tc * POSB;
    const float* hb = g_hidden + ((size_t)(n * NBLK + tc) * VV) * CC * TCHUNK;

    for (int half = 0; half < 2; half++) {
        for (int i = tid; i < VV * 32 * TCHUNK; i += 800) {
            int v = i / (32 * TCHUNK);
            int r = i % (32 * TCHUNK);          // r = o_local*32 + tl
            int ol = r >> 5, tl = r & 31;
            hs[ol * POSB + tl * VV + v] = hb[v * (CC * TCHUNK) + half * (32 * TCHUNK) + r];
        }
        __syncthreads();
        for (int cl = 0; cl < 32; cl++) {
            int c = half * 32 + cl;
            float val = hs[cl * POSB + tid];
            float xv = x[xoff + (size_t)c * (TT * VV) + tid];
            float rz = fmaf(val, g_scale[c], g_shift[c]) + xv;
            out[xoff + (size_t)c * (TT * VV) + tid] = fmaxf(rz, 0.f);
        }
        __syncthreads();
    }
}

extern "C" void kernel_launch(void* const* d_in, const int* in_sizes, int n_in,
                              void* d_out, int out_size) {
    const float* x     = (const float*)d_in[0];
    const float* A     = (const float*)d_in[1];
    const float* GA    = (const float*)d_in[2];
    const float* gw    = (const float*)d_in[7];
    const float* gb    = (const float*)d_in[8];
    const float* gamma = (const float*)d_in[9];
    const float* beta  = (const float*)d_in[10];
    float* out = (float*)d_out;
    (void)in_sizes; (void)n_in; (void)out_size;

    cudaFuncSetAttribute(k1, cudaFuncAttributeMaxDynamicSharedMemorySize, 204800);
    cudaFuncSetAttribute(k3, cudaFuncAttributeMaxDynamicSharedMemorySize, 102400);

    k0<<<1, 256>>>(A, GA, gw, gb);
    k1<<<dim3(NBLK, NN), 512, 204800>>>(x);
    k2<<<1184, 256>>>();
    kbn<<<1, 64>>>(gamma, beta);
    k3<<<dim3(NBLK, NN), 800, 102400>>>(x, out);
}

// round 2
// speedup vs baseline: 1.0105x; 1.0105x over previous
#include <cuda_runtime.h>

#define CC 64
#define TT 256
#define VV 25
#define NN 128
#define TCHUNK 32
#define POSB 800            /* TCHUNK*VV */
#define NBLK 8              /* TT/TCHUNK */
#define NPOS 819200.0f      /* NN*TT*VV */
#define TOTEL 52428800      /* NN*CC*TT*VV */

// Scratch / folded parameters (device globals: no runtime allocation)
__device__ __align__(16) float g_W[VV * CC * CC];   // [v][c][o]
__device__ __align__(16) float g_B[CC];
__device__ float g_sum[CC];
__device__ float g_sumsq[CC];
__device__ __align__(16) float g_scale[CC];
__device__ __align__(16) float g_shift[CC];
__device__ float g_hidden[TOTEL];                   // blocked layout: [blk(1024)][v(25)][o(64)][tl(32)]

__device__ __forceinline__ void ffma2(unsigned long long& d, unsigned long long a,
                                      unsigned long long b) {
    asm("fma.rn.f32x2 %0, %1, %2, %0;" : "+l"(d) : "l"(a), "l"(b));
}

// ---------------------------------------------------------------------------
// k0: fold attention rowsums into per-vertex weights.
//   s_i[v] = 1 + sum_w (A[i,v,w] + graph_attn[i,v,w])   (softmax rows sum to 1)
//   W[v][c][o] = sum_i s_i[v] * g_w[i][o][c],  B[o] = sum_i g_b[i][o]
// Also zeroes the stat accumulators for this graph replay.
// ---------------------------------------------------------------------------
__global__ void k0(const float* __restrict__ A, const float* __restrict__ GA,
                   const float* __restrict__ gw, const float* __restrict__ gb) {
    __shared__ float s_sh[3 * 25];
    int tid = threadIdx.x;
    if (tid < CC) {
        g_sum[tid] = 0.f;
        g_sumsq[tid] = 0.f;
        float b = 0.f;
        for (int i = 0; i < 3; i++) b += gb[i * CC + tid];
        g_B[tid] = b;
    }
    if (tid < 75) {
        const float* a = A + tid * 25;
        const float* g = GA + tid * 25;
        float s = 1.f;
        for (int w = 0; w < 25; w++) s += a[w] + g[w];
        s_sh[tid] = s;
    }
    __syncthreads();
    for (int idx = tid; idx < VV * CC * CC; idx += blockDim.x) {
        int v = idx >> 12;
        int r = idx & 4095;
        int c = r >> 6;
        int o = r & 63;
        float w = 0.f;
        for (int i = 0; i < 3; i++) w += s_sh[i * 25 + v] * gw[(i * CC + o) * CC + c];
        g_W[idx] = w;
    }
}

// ---------------------------------------------------------------------------
// k1: main compute. Block = (t-chunk tc, batch n). 512 threads, 16 warps.
// Stage x tile xs[c][pos] (64 x 800 floats) in smem. Warp -> vertex v
// (two rounds: v = warp, warp+16), lane -> local t. Each lane computes all 64
// output channels for its position as 32 packed f32x2 accumulators
// (o-pairs in the packed lanes; weights pre-laid [v][c][o] so a 16B load
// yields two ready-packed f32x2 weight operands — no repack movs).
// Stores raw hidden to scratch, coalesced (lane-major per o).
// ---------------------------------------------------------------------------
__global__ void __launch_bounds__(512, 1) k1(const float* __restrict__ x) {
    extern __shared__ float xs[];   // [64][800]
    int tid = threadIdx.x;
    int tc = blockIdx.x, n = blockIdx.y;
    const float* xblk = x + (size_t)n * CC * TT * VV + tc * POSB;

    // coalesced float4 staging: 64 channels x 200 float4 each
    for (int e = tid; e < CC * (POSB / 4); e += 512) {
        int c = e / (POSB / 4), q = e % (POSB / 4);
        ((float4*)xs)[c * (POSB / 4) + q] =
            ((const float4*)(xblk + (size_t)c * (TT * VV)))[q];
    }
    __syncthreads();

    int warp = tid >> 5, lane = tid & 31;
    for (int v = warp; v < VV; v += 16) {
        unsigned long long acc[32];
#pragma unroll
        for (int j = 0; j < 32; j++) {
            float2 b = ((const float2*)g_B)[j];
            asm("mov.b64 %0, {%1,%2};" : "=l"(acc[j]) : "f"(b.x), "f"(b.y));
        }
        const float* xcol = xs + lane * VV + v;           // stride 25: conflict-free
        const ulonglong2* wv = (const ulonglong2*)(g_W + v * (CC * CC));
#pragma unroll 2
        for (int c = 0; c < CC; c++) {
            float xv = xcol[c * POSB];
            unsigned long long x2;
            asm("mov.b64 %0, {%1,%1};" : "=l"(x2) : "f"(xv));
#pragma unroll
            for (int j = 0; j < 16; j++) {
                ulonglong2 w = wv[c * 16 + j];            // = {W[o4j],W[o4j+1]},{W[o4j+2],W[o4j+3]}
                ffma2(acc[2 * j], w.x, x2);
                ffma2(acc[2 * j + 1], w.y, x2);
            }
        }
        // store raw hidden: scratch[blk][v][o][lane], coalesced per o
        float* hdst = g_hidden + (((size_t)(n * NBLK + tc) * VV + v) * CC) * TCHUNK + lane;
#pragma unroll
        for (int j = 0; j < 32; j++) {
            float h0, h1;
            asm("mov.b64 {%0,%1}, %2;" : "=f"(h0), "=f"(h1) : "l"(acc[j]));
            hdst[(2 * j) * TCHUNK] = h0;
            hdst[(2 * j + 1) * TCHUNK] = h1;
        }
    }
}

// ---------------------------------------------------------------------------
// k2: per-channel sum / sumsq over scratch. Each warp owns one channel o
// (warp_id % 64), grid-strides over the 25600 (blk,v) bases, reading its
// 32-float coalesced row, then one shfl-reduce + one atomic per warp.
// 1184 blocks * 8 warps = 9472 warps = 148 warp-groups of 64.
// ---------------------------------------------------------------------------
__global__ void k2() {
    int gwid = (blockIdx.x * blockDim.x + threadIdx.x) >> 5;
    int lane = threadIdx.x & 31;
    int o = gwid & 63;
    float s = 0.f, q = 0.f;
    for (int base = gwid >> 6; base < 1024 * VV; base += 148) {
        float val = g_hidden[((size_t)base * CC + o) * TCHUNK + lane];
        s += val;
        q += val * val;
    }
#pragma unroll
    for (int d = 16; d; d >>= 1) {
        s += __shfl_xor_sync(0xffffffffu, s, d);
        q += __shfl_xor_sync(0xffffffffu, q, d);
    }
    if (lane == 0) {
        atomicAdd(&g_sum[o], s);
        atomicAdd(&g_sumsq[o], q);
    }
}

// ---------------------------------------------------------------------------
// kbn: fold batch-norm (training-mode biased stats) into scale/shift.
// ---------------------------------------------------------------------------
__global__ void kbn(const float* __restrict__ gamma, const float* __restrict__ beta) {
    int o = threadIdx.x;
    if (o < CC) {
        float m = g_sum[o] * (1.0f / NPOS);
        float var = g_sumsq[o] * (1.0f / NPOS) - m * m;
        float r = rsqrtf(var + 1e-5f);
        g_scale[o] = gamma[o] * r;
        g_shift[o] = beta[o] - m * gamma[o] * r;
    }
}

// ---------------------------------------------------------------------------
// k3: epilogue. Per block (tc, n): pull the contiguous scratch chunk through
// smem with a transpose-on-write (stride-25 stores: conflict-free), then
// fused BN + residual + relu with fully coalesced x reads / out writes.
// Split into two o-halves so smem = 100 KB -> 2 blocks/SM overlap.
// ---------------------------------------------------------------------------
__global__ void __launch_bounds__(800, 2) k3(const float* __restrict__ x,
                                             float* __restrict__ out) {
    extern __shared__ float hs[];   // [32][800]
    int tid = threadIdx.x;
    int tc = blockIdx.x, n = blockIdx.y;
    size_t xoff = (size_t)n * CC * TT * VV + tc * POSB;
    const float* hb = g_hidden + ((size_t)(n * NBLK + tc) * VV) * CC * TCHUNK;

    for (int half = 0; half < 2; half++) {
        for (int i = tid; i < VV * 32 * TCHUNK; i += 800) {
            int v = i / (32 * TCHUNK);
            int r = i % (32 * TCHUNK);          // r = o_local*32 + tl
            int ol = r >> 5, tl = r & 31;
            hs[ol * POSB + tl * VV + v] = hb[v * (CC * TCHUNK) + half * (32 * TCHUNK) + r];
        }
        __syncthreads();
        for (int cl = 0; cl < 32; cl++) {
            int c = half * 32 + cl;
            float val = hs[cl * POSB + tid];
            float xv = x[xoff + (size_t)c * (TT * VV) + tid];
            float rz = fmaf(val, g_scale[c], g_shift[c]) + xv;
            out[xoff + (size_t)c * (TT * VV) + tid] = fmaxf(rz, 0.f);
        }
        __syncthreads();
    }
}

extern "C" void kernel_launch(void* const* d_in, const int* in_sizes, int n_in,
                              void* d_out, int out_size) {
    const float* x     = (const float*)d_in[0];
    const float* A     = (const float*)d_in[1];
    const float* GA    = (const float*)d_in[2];
    const float* gw    = (const float*)d_in[7];
    const float* gb    = (const float*)d_in[8];
    const float* gamma = (const float*)d_in[9];
    const float* beta  = (const float*)d_in[10];
    float* out = (float*)d_out;
    (void)in_sizes; (void)n_in; (void)out_size;

    cudaFuncSetAttribute(k1, cudaFuncAttributeMaxDynamicSharedMemorySize, 204800);
    cudaFuncSetAttribute(k3, cudaFuncAttributeMaxDynamicSharedMemorySize, 102400);

    k0<<<1, 256>>>(A, GA, gw, gb);
    k1<<<dim3(NBLK, NN), 512, 204800>>>(x);
    k2<<<1184, 256>>>();
    kbn<<<1, 64>>>(gamma, beta);
    k3<<<dim3(NBLK, NN), 800, 102400>>>(x, out);
}